// round 2
// baseline (speedup 1.0000x reference)
#include <cuda_runtime.h>
#include <cstdint>
#include <cstddef>

// Problem dims (fixed by the dataset)
#define Bdim 64
#define Sdim 512
#define Idim 128
#define Hdim 2048
#define Odim 128
#define ALPHA 0.2f
#define NSTD  0.005f

// Scratch (device globals: sanctioned — no cudaMalloc allowed)
__device__ float g_Wt[(size_t)Hdim * Hdim];                    // alpha * g[k] * wrec[j][k], layout [j][k]
__device__ float g_hist[(size_t)Sdim * Bdim * Hdim];           // h_t history, layout [t][b][k]
__device__ float g_xp[(size_t)(Sdim - 1) * Bdim * Hdim];       // c_t = sigma*noise + alpha*x@wi, [t][b][j]

typedef unsigned long long u64;

__device__ __forceinline__ u64 ffma2(u64 a, u64 b, u64 c) {
    u64 d;
    asm("fma.rn.f32x2 %0, %1, %2, %3;" : "=l"(d) : "l"(a), "l"(b), "l"(c));
    return d;
}
__device__ __forceinline__ float hsum2(u64 a) {
    float2 f;
    f = *reinterpret_cast<float2*>(&a);
    return f.x + f.y;
}

// ---------------------------------------------------------------------------
// prep: Wt[j][k] = ALPHA * g[k] * wrec[j][k];  hist[0][b][:] = h0
// ---------------------------------------------------------------------------
__global__ void prep_kernel(const float* __restrict__ wrec,
                            const float* __restrict__ g,
                            const float* __restrict__ h0) {
    int j = blockIdx.x;
    const float* wr = wrec + (size_t)j * Hdim;
    float* wt = g_Wt + (size_t)j * Hdim;
    for (int k = threadIdx.x; k < Hdim; k += blockDim.x)
        wt[k] = ALPHA * g[k] * wr[k];
    if (j < Bdim) {
        float* h = g_hist + (size_t)j * Hdim;   // t = 0
        for (int k = threadIdx.x; k < Hdim; k += blockDim.x)
            h[k] = h0[k];
    }
}

// ---------------------------------------------------------------------------
// xp: for t in [0, S-1): xp[t][b][j] = NSTD*noise[b][t][j] + ALPHA * sum_i x[b][t][i]*wi[i][j]
// GEMM tile 64x64, K=128 (two BK=64 slabs). 256 threads, 16 outs/thread.
// ---------------------------------------------------------------------------
__global__ void xp_kernel(const float* __restrict__ x,
                          const float* __restrict__ noise,
                          const float* __restrict__ wi) {
    __shared__ float sx[64][68];
    __shared__ float sw[64][68];
    int t  = blockIdx.y;
    int c0 = blockIdx.x * 64;
    int tid = threadIdx.x;
    int tx = tid & 15, ty = tid >> 4;      // 16x16 thread grid, interleaved blocking

    u64 acc[4][4];
    #pragma unroll
    for (int i = 0; i < 4; i++)
        #pragma unroll
        for (int j = 0; j < 4; j++) acc[i][j] = 0ull;

    for (int k0 = 0; k0 < Idim; k0 += 64) {
        // load x tile: rows b=0..63, cols k0..k0+63
        #pragma unroll
        for (int i = 0; i < 4; i++) {
            int idx = tid + 256 * i;
            int b = idx >> 4, q = idx & 15;
            float4 v = *(const float4*)(x + ((size_t)b * Sdim + t) * Idim + k0 + q * 4);
            *(float4*)&sx[b][q * 4] = v;
        }
        // load wi tile transposed: sw[c][k] = wi[k0+k][c0+c]
        #pragma unroll
        for (int i = 0; i < 4; i++) {
            int idx = tid + 256 * i;
            int kr = idx >> 4, q = idx & 15;
            float4 v = *(const float4*)(wi + ((size_t)(k0 + kr)) * Hdim + c0 + q * 4);
            sw[q * 4 + 0][kr] = v.x;
            sw[q * 4 + 1][kr] = v.y;
            sw[q * 4 + 2][kr] = v.z;
            sw[q * 4 + 3][kr] = v.w;
        }
        __syncthreads();
        #pragma unroll
        for (int kb = 0; kb < 64; kb += 2) {
            u64 ha[4], wb[4];
            #pragma unroll
            for (int i = 0; i < 4; i++) ha[i] = *(const u64*)&sx[ty + 16 * i][kb];
            #pragma unroll
            for (int j = 0; j < 4; j++) wb[j] = *(const u64*)&sw[tx + 16 * j][kb];
            #pragma unroll
            for (int i = 0; i < 4; i++)
                #pragma unroll
                for (int j = 0; j < 4; j++)
                    acc[i][j] = ffma2(ha[i], wb[j], acc[i][j]);
        }
        __syncthreads();
    }

    #pragma unroll
    for (int i = 0; i < 4; i++) {
        int b = ty + 16 * i;
        #pragma unroll
        for (int j = 0; j < 4; j++) {
            int jc = c0 + tx + 16 * j;
            float s = hsum2(acc[i][j]);
            float n = noise[((size_t)b * Sdim + t) * Hdim + jc];
            g_xp[((size_t)t * Bdim + b) * Hdim + jc] = NSTD * n + ALPHA * s;
        }
    }
}

// ---------------------------------------------------------------------------
// step t: hist[t+1][b][j] = (1-ALPHA)*hist[t][b][j] + sum_k hist[t][b][k]*Wt[j][k] + xp[t][b][j]
// 128 CTAs (16 output cols each), tile 64x16, 256 threads, 4 outs/thread.
// ---------------------------------------------------------------------------
__global__ void step_kernel(int t) {
    __shared__ float sh[64][68];
    __shared__ float sw[16][68];
    int c0 = blockIdx.x * 16;
    int tid = threadIdx.x;
    int tx = tid & 7, ty = tid >> 3;       // tx: 0..7 (cols, interleaved by 8); ty: 0..31 (rows, by 32)

    u64 a00 = 0ull, a01 = 0ull, a10 = 0ull, a11 = 0ull;
    const float* hin = g_hist + (size_t)t * Bdim * Hdim;

    for (int k0 = 0; k0 < Hdim; k0 += 64) {
        #pragma unroll
        for (int i = 0; i < 4; i++) {
            int idx = tid + 256 * i;
            int b = idx >> 4, q = idx & 15;
            *(float4*)&sh[b][q * 4] = *(const float4*)(hin + (size_t)b * Hdim + k0 + q * 4);
        }
        {
            int r = tid >> 4, q = tid & 15;
            *(float4*)&sw[r][q * 4] = *(const float4*)(g_Wt + (size_t)(c0 + r) * Hdim + k0 + q * 4);
        }
        __syncthreads();
        #pragma unroll
        for (int kb = 0; kb < 64; kb += 2) {
            u64 h0 = *(const u64*)&sh[ty][kb];
            u64 h1 = *(const u64*)&sh[ty + 32][kb];
            u64 w0 = *(const u64*)&sw[tx][kb];
            u64 w1 = *(const u64*)&sw[tx + 8][kb];
            a00 = ffma2(h0, w0, a00);
            a01 = ffma2(h0, w1, a01);
            a10 = ffma2(h1, w0, a10);
            a11 = ffma2(h1, w1, a11);
        }
        __syncthreads();
    }

    float* hout = g_hist + (size_t)(t + 1) * Bdim * Hdim;
    const float* xp = g_xp + (size_t)t * Bdim * Hdim;
    u64 accs[2][2] = {{a00, a01}, {a10, a11}};
    #pragma unroll
    for (int i = 0; i < 2; i++) {
        int b = ty + 32 * i;
        #pragma unroll
        for (int j = 0; j < 2; j++) {
            int jc = c0 + tx + 8 * j;
            size_t off = (size_t)b * Hdim + jc;
            float s = hsum2(accs[i][j]);
            hout[off] = (1.0f - ALPHA) * hin[off] + s + xp[off];
        }
    }
}

// ---------------------------------------------------------------------------
// out: out[b][t][o] = sum_k hist[t][b][k] * wout[k][o]
// grid (O/64, S), tile 64x64, K=2048.
// ---------------------------------------------------------------------------
__global__ void out_kernel(const float* __restrict__ wout,
                           float* __restrict__ out) {
    __shared__ float sh[64][68];
    __shared__ float sw[64][68];
    int t  = blockIdx.y;
    int c0 = blockIdx.x * 64;
    int tid = threadIdx.x;
    int tx = tid & 15, ty = tid >> 4;

    u64 acc[4][4];
    #pragma unroll
    for (int i = 0; i < 4; i++)
        #pragma unroll
        for (int j = 0; j < 4; j++) acc[i][j] = 0ull;

    const float* hin = g_hist + (size_t)t * Bdim * Hdim;

    for (int k0 = 0; k0 < Hdim; k0 += 64) {
        #pragma unroll
        for (int i = 0; i < 4; i++) {
            int idx = tid + 256 * i;
            int b = idx >> 4, q = idx & 15;
            *(float4*)&sh[b][q * 4] = *(const float4*)(hin + (size_t)b * Hdim + k0 + q * 4);
        }
        #pragma unroll
        for (int i = 0; i < 4; i++) {
            int idx = tid + 256 * i;
            int kr = idx >> 4, q = idx & 15;
            float4 v = *(const float4*)(wout + ((size_t)(k0 + kr)) * Odim + c0 + q * 4);
            sw[q * 4 + 0][kr] = v.x;
            sw[q * 4 + 1][kr] = v.y;
            sw[q * 4 + 2][kr] = v.z;
            sw[q * 4 + 3][kr] = v.w;
        }
        __syncthreads();
        #pragma unroll
        for (int kb = 0; kb < 64; kb += 2) {
            u64 ha[4], wb[4];
            #pragma unroll
            for (int i = 0; i < 4; i++) ha[i] = *(const u64*)&sh[ty + 16 * i][kb];
            #pragma unroll
            for (int j = 0; j < 4; j++) wb[j] = *(const u64*)&sw[tx + 16 * j][kb];
            #pragma unroll
            for (int i = 0; i < 4; i++)
                #pragma unroll
                for (int j = 0; j < 4; j++)
                    acc[i][j] = ffma2(ha[i], wb[j], acc[i][j]);
        }
        __syncthreads();
    }

    #pragma unroll
    for (int i = 0; i < 4; i++) {
        int b = ty + 16 * i;
        #pragma unroll
        for (int j = 0; j < 4; j++) {
            int o = c0 + tx + 16 * j;
            out[((size_t)b * Sdim + t) * Odim + o] = hsum2(acc[i][j]);
        }
    }
}

// ---------------------------------------------------------------------------
extern "C" void kernel_launch(void* const* d_in, const int* in_sizes, int n_in,
                              void* d_out, int out_size) {
    const float* x     = (const float*)d_in[0];   // (64, 512, 128)
    const float* noise = (const float*)d_in[1];   // (64, 512, 2048)
    const float* wi    = (const float*)d_in[2];   // (128, 2048)
    const float* wrec  = (const float*)d_in[3];   // (2048, 2048)
    const float* wout  = (const float*)d_in[4];   // (2048, 128)
    const float* g     = (const float*)d_in[5];   // (2048, 1)
    const float* h0    = (const float*)d_in[6];   // (2048,)
    float* out = (float*)d_out;                   // (64, 512, 128)

    prep_kernel<<<Hdim, 256>>>(wrec, g, h0);
    xp_kernel<<<dim3(Hdim / 64, Sdim - 1), 256>>>(x, noise, wi);
    for (int t = 0; t < Sdim - 1; t++)
        step_kernel<<<Hdim / 16, 256>>>(t);
    out_kernel<<<dim3(Odim / 64, Sdim), 256>>>(wout, out);
}